// round 5
// baseline (speedup 1.0000x reference)
#include <cuda_runtime.h>
#include <cuda_bf16.h>
#include <stdint.h>

#define N_ENT 4096
#define FDIM  512
#define CELLS 39
#define PAIRS 8192

// ---------------- scratch (device globals: allocation-free rule) ----------------
__device__ __nv_bfloat16 g_Ehi[N_ENT * FDIM];               // 4 MB
__device__ __nv_bfloat16 g_Elo[N_ENT * FDIM];               // 4 MB
__device__ __nv_bfloat16 g_Bhi[CELLS * FDIM * FDIM];        // 20 MB  [c][kout][n] = wl[c,n]*W[n,kout]
__device__ __nv_bfloat16 g_Blo[CELLS * FDIM * FDIM];        // 20 MB
__device__ float         g_T[(size_t)CELLS * N_ENT * FDIM]; // 327 MB T'_c = (E @ Wc) * wl[c,k]

// ---------------- small helpers ----------------
__device__ __forceinline__ uint32_t smem_to_u32(const void* p) {
    uint32_t a;
    asm("{ .reg .u64 t; cvta.to.shared.u64 t, %1; cvt.u32.u64 %0, t; }" : "=r"(a) : "l"(p));
    return a;
}
__device__ __forceinline__ void cp_async16(uint32_t dst, const void* src) {
    asm volatile("cp.async.cg.shared.global [%0], [%1], 16;" :: "r"(dst), "l"(src));
}
#define CP_COMMIT() asm volatile("cp.async.commit_group;" ::: "memory")
#define CP_WAIT(n)  asm volatile("cp.async.wait_group %0;" :: "n"(n) : "memory")

#define LDSM_X4(r, addr) \
    asm volatile("ldmatrix.sync.aligned.m8n8.x4.shared.b16 {%0,%1,%2,%3}, [%4];" \
        : "=r"((r)[0]), "=r"((r)[1]), "=r"((r)[2]), "=r"((r)[3]) : "r"(addr))

__device__ __forceinline__ void mma16816(float* c, const uint32_t* a, uint32_t b0, uint32_t b1) {
    asm volatile("mma.sync.aligned.m16n8k16.row.col.f32.bf16.bf16.f32 "
                 "{%0,%1,%2,%3}, {%4,%5,%6,%7}, {%8,%9}, {%0,%1,%2,%3};"
                 : "+f"(c[0]), "+f"(c[1]), "+f"(c[2]), "+f"(c[3])
                 : "r"(a[0]), "r"(a[1]), "r"(a[2]), "r"(a[3]), "r"(b0), "r"(b1));
}

__device__ __forceinline__ void split_bf16(float x, __nv_bfloat16& h, __nv_bfloat16& l) {
    h = __float2bfloat16(x);
    l = __float2bfloat16(x - __bfloat162float(h));
}

// ---------------- prep kernels ----------------
__global__ void prep_split_E(const float* __restrict__ emb) {
    for (int i = blockIdx.x * blockDim.x + threadIdx.x; i < N_ENT * FDIM; i += gridDim.x * blockDim.x) {
        __nv_bfloat16 h, l;
        split_bf16(emb[i], h, l);
        g_Ehi[i] = h;
        g_Elo[i] = l;
    }
}

// g_B{hi,lo}[c][kout][n] = split( wl[c,n] * W[n,kout] )  — transpose via smem tile
__global__ void prep_W(const float* __restrict__ W, const float* __restrict__ wl) {
    __shared__ float sW[32][33];
    int tx = threadIdx.x, ty = threadIdx.y;
    int n0 = blockIdx.x * 32, k0 = blockIdx.y * 32;
    sW[ty][tx] = W[(n0 + ty) * FDIM + (k0 + tx)];   // coalesced read
    __syncthreads();
    float wv = sW[tx][ty];                           // = W[n0+tx][k0+ty]
    int oidx = (k0 + ty) * FDIM + (n0 + tx);
    for (int c = 0; c < CELLS; c++) {
        float v = wl[c * FDIM + n0 + tx] * wv;
        __nv_bfloat16 h, l;
        split_bf16(v, h, l);
        g_Bhi[c * FDIM * FDIM + oidx] = h;           // coalesced write (tx fast)
        g_Blo[c * FDIM * FDIM + oidx] = l;
    }
}

// ---------------- GEMM: T'_c = (E @ Wc) * wl[c,:] via mma.sync bf16 3-term split ----------------
// CTA tile M=128, N=128, BK=64, 512 threads (16 warps: 4 in M x 4 in N, warp tile 32x32).
// 4 warps/SMSP for latency hiding (2 warps/SMSP was issue-starved: 13.7 cyc/mma).
// SMEM rows padded to 144B -> conflict-free ldmatrix.
#define BK          64
#define NKC         (FDIM / BK)       // 8 chunks
#define ROW_S       144
#define TILE_BYTES  (128 * ROW_S)     // 18432
#define A_HI        0
#define A_LO        (1 * TILE_BYTES)
#define B_HI        (2 * TILE_BYTES)
#define B_LO        (3 * TILE_BYTES)
#define BUF_BYTES   (4 * TILE_BYTES)  // 73728
#define GEMM_SMEM   (2 * BUF_BYTES)   // 147456
#define NTHREADS    512

__device__ __forceinline__ void load_buf(uint32_t smem_u, int buf, int kc, int tid,
                                         const char* eh, const char* el,
                                         const char* bh, const char* bl) {
    const char* srcs[4] = { eh, el, bh, bl };
    uint32_t dbase = smem_u + buf * BUF_BYTES;
    #pragma unroll
    for (int t = 0; t < 4; t++) {
        uint32_t dt = dbase + t * TILE_BYTES;
        const char* s = srcs[t] + (size_t)kc * (BK * 2);
        #pragma unroll
        for (int i = 0; i < 2; i++) {
            int v = i * NTHREADS + tid;      // 0..1023
            int row = v >> 3, seg = v & 7;   // 128 rows x 8 x 16B
            cp_async16(dt + row * ROW_S + seg * 16,
                       s + (size_t)row * (FDIM * 2) + seg * 16);
        }
    }
}

__global__ void __launch_bounds__(NTHREADS, 1)
gemm_kernel(const float* __restrict__ wl) {
    extern __shared__ char smem[];
    uint32_t smem_u = smem_to_u32(smem);

    const int tid = threadIdx.x;
    const int wid = tid >> 5, lane = tid & 31;
    const int warp_m = wid & 3;        // 0..3 -> rows warp_m*32
    const int warp_n = wid >> 2;       // 0..3 -> cols warp_n*32
    const int mt = blockIdx.x, nt = blockIdx.y, c = blockIdx.z;

    const char* eh = (const char*)g_Ehi + (size_t)(mt * 128) * (FDIM * 2);
    const char* el = (const char*)g_Elo + (size_t)(mt * 128) * (FDIM * 2);
    const char* bh = (const char*)g_Bhi + ((size_t)c * FDIM + nt * 128) * (FDIM * 2);
    const char* bl = (const char*)g_Blo + ((size_t)c * FDIM + nt * 128) * (FDIM * 2);

    float acc[2][4][4];
    #pragma unroll
    for (int i = 0; i < 2; i++)
        #pragma unroll
        for (int j = 0; j < 4; j++)
            #pragma unroll
            for (int q = 0; q < 4; q++) acc[i][j][q] = 0.f;

    const int lr = lane & 15;          // ldmatrix row within 16-row group
    const int lcb = (lane >> 4) * 16;  // col-block byte offset (0 or 16)

    load_buf(smem_u, 0, 0, tid, eh, el, bh, bl);
    CP_COMMIT();

    for (int kc = 0; kc < NKC; kc++) {
        int buf = kc & 1;
        if (kc + 1 < NKC) {
            load_buf(smem_u, buf ^ 1, kc + 1, tid, eh, el, bh, bl);
            CP_COMMIT();
            CP_WAIT(1);
        } else {
            CP_WAIT(0);
        }
        __syncthreads();

        uint32_t base = smem_u + buf * BUF_BYTES;
        uint32_t aRow = base + (warp_m * 32 + lr) * ROW_S + lcb;
        uint32_t bRow = base + B_HI + (warp_n * 32 + lr) * ROW_S + lcb;

        #pragma unroll
        for (int k16 = 0; k16 < BK / 16; k16++) {
            uint32_t ko = k16 * 32;    // 16 bf16 = 32B
            uint32_t ah[2][4], al[2][4], bhf[2][4], blf[2][4];
            #pragma unroll
            for (int mi = 0; mi < 2; mi++) {
                LDSM_X4(ah[mi], aRow + A_HI + mi * (16 * ROW_S) + ko);
                LDSM_X4(al[mi], aRow + A_LO + mi * (16 * ROW_S) + ko);
            }
            #pragma unroll
            for (int nj = 0; nj < 2; nj++) {
                LDSM_X4(bhf[nj], bRow + nj * (16 * ROW_S) + ko);
                LDSM_X4(blf[nj], bRow + TILE_BYTES + nj * (16 * ROW_S) + ko);
            }
            #pragma unroll
            for (int mi = 0; mi < 2; mi++)
                #pragma unroll
                for (int n = 0; n < 4; n++) {
                    int nj = n >> 1, hf = n & 1;
                    mma16816(acc[mi][n], ah[mi], bhf[nj][hf], bhf[nj][hf + 2]);
                    mma16816(acc[mi][n], ah[mi], blf[nj][hf], blf[nj][hf + 2]);
                    mma16816(acc[mi][n], al[mi], bhf[nj][hf], bhf[nj][hf + 2]);
                }
        }
        __syncthreads();
    }

    // epilogue: scale by wl[c, kout], write fp32 T'
    const int gid = lane >> 2, tq = lane & 3;
    const int row0 = mt * 128 + warp_m * 32 + gid;
    const int col0 = nt * 128 + warp_n * 32 + tq * 2;
    #pragma unroll
    for (int n = 0; n < 4; n++) {
        int cg = col0 + n * 8;
        float w0 = __ldg(&wl[c * FDIM + cg]);
        float w1 = __ldg(&wl[c * FDIM + cg + 1]);
        #pragma unroll
        for (int mi = 0; mi < 2; mi++) {
            int r = row0 + mi * 16;
            float* o0 = g_T + ((size_t)c * N_ENT + r) * FDIM + cg;
            float* o1 = g_T + ((size_t)c * N_ENT + r + 8) * FDIM + cg;
            float2 v0 = make_float2(acc[mi][n][0] * w0, acc[mi][n][1] * w1);
            float2 v1 = make_float2(acc[mi][n][2] * w0, acc[mi][n][3] * w1);
            *(float2*)o0 = v0;
            *(float2*)o1 = v1;
        }
    }
}

// ---------------- gather-dot: out[c,p] = dot(T'_c[i0,:], E[i1,:]) ----------------
__global__ void __launch_bounds__(256) gather_kernel(const int* __restrict__ index,
                                                     const float* __restrict__ emb,
                                                     float* __restrict__ out) {
    int gw = (blockIdx.x * blockDim.x + threadIdx.x) >> 5;
    int lane = threadIdx.x & 31;
    int p0 = gw * 2;
    int c = p0 / PAIRS, p = p0 - c * PAIRS;
    int2 ipA = __ldg((const int2*)index + (size_t)c * PAIRS + p);
    int2 ipB = __ldg((const int2*)index + (size_t)c * PAIRS + p + 1);
    const float4* aA = (const float4*)(g_T + ((size_t)c * N_ENT + ipA.x) * FDIM);
    const float4* bA = (const float4*)(emb + (size_t)ipA.y * FDIM);
    const float4* aB = (const float4*)(g_T + ((size_t)c * N_ENT + ipB.x) * FDIM);
    const float4* bB = (const float4*)(emb + (size_t)ipB.y * FDIM);
    float accA = 0.f, accB = 0.f;
    #pragma unroll
    for (int j = 0; j < 4; j++) {
        float4 xA = __ldg(aA + lane + j * 32);
        float4 yA = __ldg(bA + lane + j * 32);
        float4 xB = __ldg(aB + lane + j * 32);
        float4 yB = __ldg(bB + lane + j * 32);
        accA += xA.x * yA.x + xA.y * yA.y + xA.z * yA.z + xA.w * yA.w;
        accB += xB.x * yB.x + xB.y * yB.y + xB.z * yB.z + xB.w * yB.w;
    }
    #pragma unroll
    for (int o = 16; o; o >>= 1) {
        accA += __shfl_xor_sync(0xffffffffu, accA, o);
        accB += __shfl_xor_sync(0xffffffffu, accB, o);
    }
    if (lane == 0) {
        out[(size_t)c * PAIRS + p]     = accA;
        out[(size_t)c * PAIRS + p + 1] = accB;
    }
}

// ---------------- launch ----------------
extern "C" void kernel_launch(void* const* d_in, const int* in_sizes, int n_in,
                              void* d_out, int out_size) {
    const float* emb   = (const float*)d_in[0];   // [4096, 512] f32
    const int*   index = (const int*)d_in[1];     // [39, 8192, 2] i32
    const float* W     = (const float*)d_in[2];   // [512, 512] f32
    const float* wl    = (const float*)d_in[3];   // [39, 512] f32
    float* out = (float*)d_out;                   // [39, 8192] f32

    cudaFuncSetAttribute(gemm_kernel, cudaFuncAttributeMaxDynamicSharedMemorySize, GEMM_SMEM);

    prep_split_E<<<1024, 256>>>(emb);
    prep_W<<<dim3(FDIM / 32, FDIM / 32), dim3(32, 32)>>>(W, wl);
    gemm_kernel<<<dim3(N_ENT / 128, FDIM / 128, CELLS), NTHREADS, GEMM_SMEM>>>(wl);
    gather_kernel<<<(CELLS * PAIRS) / 16, 256>>>(index, emb, out);
}

// round 6
// speedup vs baseline: 1.3043x; 1.3043x over previous
#include <cuda_runtime.h>
#include <cuda_bf16.h>
#include <stdint.h>

#define N_ENT 4096
#define FDIM  512
#define CELLS 39
#define PAIRS 8192

// ---------------- scratch (device globals: allocation-free rule) ----------------
__device__ __nv_bfloat16 g_Ehi[N_ENT * FDIM];               // 4 MB
__device__ __nv_bfloat16 g_Elo[N_ENT * FDIM];               // 4 MB
__device__ __nv_bfloat16 g_Bhi[CELLS * FDIM * FDIM];        // 20 MB  [c][kout][n] = wl[c,n]*W[n,kout]
__device__ __nv_bfloat16 g_Blo[CELLS * FDIM * FDIM];        // 20 MB
__device__ float         g_T[(size_t)CELLS * N_ENT * FDIM]; // 327 MB T'_c = (E @ Wc) * wl[c,k]

// ---------------- small helpers ----------------
__device__ __forceinline__ uint32_t smem_to_u32(const void* p) {
    uint32_t a;
    asm("{ .reg .u64 t; cvta.to.shared.u64 t, %1; cvt.u32.u64 %0, t; }" : "=r"(a) : "l"(p));
    return a;
}
__device__ __forceinline__ void cp_async16(uint32_t dst, const void* src) {
    asm volatile("cp.async.cg.shared.global [%0], [%1], 16;" :: "r"(dst), "l"(src));
}
#define CP_COMMIT() asm volatile("cp.async.commit_group;" ::: "memory")
#define CP_WAIT(n)  asm volatile("cp.async.wait_group %0;" :: "n"(n) : "memory")

#define LDSM_X4(r, addr) \
    asm volatile("ldmatrix.sync.aligned.m8n8.x4.shared.b16 {%0,%1,%2,%3}, [%4];" \
        : "=r"((r)[0]), "=r"((r)[1]), "=r"((r)[2]), "=r"((r)[3]) : "r"(addr))

__device__ __forceinline__ void mma16816(float* c, const uint32_t* a, uint32_t b0, uint32_t b1) {
    asm volatile("mma.sync.aligned.m16n8k16.row.col.f32.bf16.bf16.f32 "
                 "{%0,%1,%2,%3}, {%4,%5,%6,%7}, {%8,%9}, {%0,%1,%2,%3};"
                 : "+f"(c[0]), "+f"(c[1]), "+f"(c[2]), "+f"(c[3])
                 : "r"(a[0]), "r"(a[1]), "r"(a[2]), "r"(a[3]), "r"(b0), "r"(b1));
}

__device__ __forceinline__ void split_bf16(float x, __nv_bfloat16& h, __nv_bfloat16& l) {
    h = __float2bfloat16(x);
    l = __float2bfloat16(x - __bfloat162float(h));
}

// ---------------- prep kernels ----------------
__global__ void prep_split_E(const float* __restrict__ emb) {
    for (int i = blockIdx.x * blockDim.x + threadIdx.x; i < N_ENT * FDIM; i += gridDim.x * blockDim.x) {
        __nv_bfloat16 h, l;
        split_bf16(emb[i], h, l);
        g_Ehi[i] = h;
        g_Elo[i] = l;
    }
}

// g_B{hi,lo}[c][kout][n] = split( wl[c,n] * W[n,kout] )  — transpose via smem tile
__global__ void prep_W(const float* __restrict__ W, const float* __restrict__ wl) {
    __shared__ float sW[32][33];
    int tx = threadIdx.x, ty = threadIdx.y;
    int n0 = blockIdx.x * 32, k0 = blockIdx.y * 32;
    sW[ty][tx] = W[(n0 + ty) * FDIM + (k0 + tx)];   // coalesced read
    __syncthreads();
    float wv = sW[tx][ty];                           // = W[n0+tx][k0+ty]
    int oidx = (k0 + ty) * FDIM + (n0 + tx);
    for (int c = 0; c < CELLS; c++) {
        float v = wl[c * FDIM + n0 + tx] * wv;
        __nv_bfloat16 h, l;
        split_bf16(v, h, l);
        g_Bhi[c * FDIM * FDIM + oidx] = h;           // coalesced write (tx fast)
        g_Blo[c * FDIM * FDIM + oidx] = l;
    }
}

// ---------------- GEMM: T'_c = (E @ Wc) * wl[c,:] via mma.sync bf16 3-term split ----------------
// CTA tile M=128, N=256, BK=64, 256 threads (8 warps: 2 in M x 4 in N, warp tile 64x64).
// ldsm:mma ratio 1:6 (was 1:4) — the R2..R5 series showed time tracks ldsm count.
// SMEM rows padded to 144B -> conflict-free ldmatrix.
#define BK          64
#define NKC         (FDIM / BK)       // 8 chunks
#define ROW_S       144
#define A_TILE      (128 * ROW_S)     // 18432
#define B_TILE      (256 * ROW_S)     // 36864
#define A_HI        0
#define A_LO        (A_TILE)
#define B_HI        (2 * A_TILE)
#define B_LO        (2 * A_TILE + B_TILE)
#define BUF_BYTES   (2 * A_TILE + 2 * B_TILE)   // 110592
#define GEMM_SMEM   (2 * BUF_BYTES)             // 221184

__device__ __forceinline__ void load_buf(uint32_t smem_u, int buf, int kc, int tid,
                                         const char* eh, const char* el,
                                         const char* bh, const char* bl) {
    uint32_t dbase = smem_u + buf * BUF_BYTES;
    // A tiles: 128 rows x 8 segs = 1024 vecs each
    {
        const char* sA[2] = { eh, el };
        #pragma unroll
        for (int t = 0; t < 2; t++) {
            uint32_t dt = dbase + t * A_TILE;
            const char* s = sA[t] + (size_t)kc * (BK * 2);
            #pragma unroll
            for (int i = 0; i < 4; i++) {
                int v = i * 256 + tid;
                int row = v >> 3, seg = v & 7;
                cp_async16(dt + row * ROW_S + seg * 16,
                           s + (size_t)row * (FDIM * 2) + seg * 16);
            }
        }
    }
    // B tiles: 256 rows x 8 segs = 2048 vecs each
    {
        const char* sB[2] = { bh, bl };
        #pragma unroll
        for (int t = 0; t < 2; t++) {
            uint32_t dt = dbase + B_HI + t * B_TILE;
            const char* s = sB[t] + (size_t)kc * (BK * 2);
            #pragma unroll
            for (int i = 0; i < 8; i++) {
                int v = i * 256 + tid;
                int row = v >> 3, seg = v & 7;
                cp_async16(dt + row * ROW_S + seg * 16,
                           s + (size_t)row * (FDIM * 2) + seg * 16);
            }
        }
    }
}

__global__ void __launch_bounds__(256, 1)
gemm_kernel(const float* __restrict__ wl) {
    extern __shared__ char smem[];
    uint32_t smem_u = smem_to_u32(smem);

    const int tid = threadIdx.x;
    const int wid = tid >> 5, lane = tid & 31;
    const int warp_m = wid & 1;        // 0..1 -> rows warp_m*64
    const int warp_n = wid >> 1;       // 0..3 -> cols warp_n*64
    const int mt = blockIdx.x, nt = blockIdx.y, c = blockIdx.z;

    const char* eh = (const char*)g_Ehi + (size_t)(mt * 128) * (FDIM * 2);
    const char* el = (const char*)g_Elo + (size_t)(mt * 128) * (FDIM * 2);
    const char* bh = (const char*)g_Bhi + ((size_t)c * FDIM + nt * 256) * (FDIM * 2);
    const char* bl = (const char*)g_Blo + ((size_t)c * FDIM + nt * 256) * (FDIM * 2);

    float acc[4][8][4];
    #pragma unroll
    for (int i = 0; i < 4; i++)
        #pragma unroll
        for (int j = 0; j < 8; j++)
            #pragma unroll
            for (int q = 0; q < 4; q++) acc[i][j][q] = 0.f;

    const int lr = lane & 15;          // ldmatrix row within 16-row group
    const int lcb = (lane >> 4) * 16;  // col-block byte offset (0 or 16)

    load_buf(smem_u, 0, 0, tid, eh, el, bh, bl);
    CP_COMMIT();

    for (int kc = 0; kc < NKC; kc++) {
        int buf = kc & 1;
        if (kc + 1 < NKC) {
            load_buf(smem_u, buf ^ 1, kc + 1, tid, eh, el, bh, bl);
            CP_COMMIT();
            CP_WAIT(1);
        } else {
            CP_WAIT(0);
        }
        __syncthreads();

        uint32_t base = smem_u + buf * BUF_BYTES;
        uint32_t aRow = base + (warp_m * 64 + lr) * ROW_S + lcb;
        uint32_t bRow = base + B_HI + (warp_n * 64 + lr) * ROW_S + lcb;

        #pragma unroll
        for (int k16 = 0; k16 < BK / 16; k16++) {
            uint32_t ko = k16 * 32;    // 16 bf16 = 32B
            uint32_t ah[4][4], al[4][4], bhf[4][4], blf[4][4];
            #pragma unroll
            for (int mi = 0; mi < 4; mi++) {
                LDSM_X4(ah[mi], aRow + A_HI + mi * (16 * ROW_S) + ko);
                LDSM_X4(al[mi], aRow + A_LO + mi * (16 * ROW_S) + ko);
            }
            #pragma unroll
            for (int nj = 0; nj < 4; nj++) {
                LDSM_X4(bhf[nj], bRow + nj * (16 * ROW_S) + ko);
                LDSM_X4(blf[nj], bRow + B_TILE + nj * (16 * ROW_S) + ko);
            }
            #pragma unroll
            for (int mi = 0; mi < 4; mi++)
                #pragma unroll
                for (int n = 0; n < 8; n++) {
                    int nj = n >> 1, hf = n & 1;
                    mma16816(acc[mi][n], ah[mi], bhf[nj][hf], bhf[nj][hf + 2]);
                    mma16816(acc[mi][n], ah[mi], blf[nj][hf], blf[nj][hf + 2]);
                    mma16816(acc[mi][n], al[mi], bhf[nj][hf], bhf[nj][hf + 2]);
                }
        }
        __syncthreads();
    }

    // epilogue: scale by wl[c, kout], write fp32 T'
    const int gid = lane >> 2, tq = lane & 3;
    const int row0 = mt * 128 + warp_m * 64 + gid;
    const int col0 = nt * 256 + warp_n * 64 + tq * 2;
    #pragma unroll
    for (int n = 0; n < 8; n++) {
        int cg = col0 + n * 8;
        float w0 = __ldg(&wl[c * FDIM + cg]);
        float w1 = __ldg(&wl[c * FDIM + cg + 1]);
        #pragma unroll
        for (int mi = 0; mi < 4; mi++) {
            int r = row0 + mi * 16;
            float* o0 = g_T + ((size_t)c * N_ENT + r) * FDIM + cg;
            float* o1 = g_T + ((size_t)c * N_ENT + r + 8) * FDIM + cg;
            float2 v0 = make_float2(acc[mi][n][0] * w0, acc[mi][n][1] * w1);
            float2 v1 = make_float2(acc[mi][n][2] * w0, acc[mi][n][3] * w1);
            *(float2*)o0 = v0;
            *(float2*)o1 = v1;
        }
    }
}

// ---------------- gather-dot: out[c,p] = dot(T'_c[i0,:], E[i1,:]) ----------------
__global__ void __launch_bounds__(256) gather_kernel(const int* __restrict__ index,
                                                     const float* __restrict__ emb,
                                                     float* __restrict__ out) {
    int gw = (blockIdx.x * blockDim.x + threadIdx.x) >> 5;
    int lane = threadIdx.x & 31;
    int p0 = gw * 2;
    int c = p0 / PAIRS, p = p0 - c * PAIRS;
    int2 ipA = __ldg((const int2*)index + (size_t)c * PAIRS + p);
    int2 ipB = __ldg((const int2*)index + (size_t)c * PAIRS + p + 1);
    const float4* aA = (const float4*)(g_T + ((size_t)c * N_ENT + ipA.x) * FDIM);
    const float4* bA = (const float4*)(emb + (size_t)ipA.y * FDIM);
    const float4* aB = (const float4*)(g_T + ((size_t)c * N_ENT + ipB.x) * FDIM);
    const float4* bB = (const float4*)(emb + (size_t)ipB.y * FDIM);
    float accA = 0.f, accB = 0.f;
    #pragma unroll
    for (int j = 0; j < 4; j++) {
        float4 xA = __ldg(aA + lane + j * 32);
        float4 yA = __ldg(bA + lane + j * 32);
        float4 xB = __ldg(aB + lane + j * 32);
        float4 yB = __ldg(bB + lane + j * 32);
        accA += xA.x * yA.x + xA.y * yA.y + xA.z * yA.z + xA.w * yA.w;
        accB += xB.x * yB.x + xB.y * yB.y + xB.z * yB.z + xB.w * yB.w;
    }
    #pragma unroll
    for (int o = 16; o; o >>= 1) {
        accA += __shfl_xor_sync(0xffffffffu, accA, o);
        accB += __shfl_xor_sync(0xffffffffu, accB, o);
    }
    if (lane == 0) {
        out[(size_t)c * PAIRS + p]     = accA;
        out[(size_t)c * PAIRS + p + 1] = accB;
    }
}

// ---------------- launch ----------------
extern "C" void kernel_launch(void* const* d_in, const int* in_sizes, int n_in,
                              void* d_out, int out_size) {
    const float* emb   = (const float*)d_in[0];   // [4096, 512] f32
    const int*   index = (const int*)d_in[1];     // [39, 8192, 2] i32
    const float* W     = (const float*)d_in[2];   // [512, 512] f32
    const float* wl    = (const float*)d_in[3];   // [39, 512] f32
    float* out = (float*)d_out;                   // [39, 8192] f32

    cudaFuncSetAttribute(gemm_kernel, cudaFuncAttributeMaxDynamicSharedMemorySize, GEMM_SMEM);

    prep_split_E<<<1024, 256>>>(emb);
    prep_W<<<dim3(FDIM / 32, FDIM / 32), dim3(32, 32)>>>(W, wl);
    gemm_kernel<<<dim3(N_ENT / 128, FDIM / 256, CELLS), 256, GEMM_SMEM>>>(wl);
    gather_kernel<<<(CELLS * PAIRS) / 16, 256>>>(index, emb, out);
}